// round 7
// baseline (speedup 1.0000x reference)
#include <cuda_runtime.h>

// Problem constants
#define Bb 4
#define Ss 2048
#define Dd 1024
#define Hh 16
#define DHd 64
#define TOK (Bb*Ss)          // 8192
#define NHD (Hh*DHd)         // 1024

// Scratch (device globals — no allocation allowed in kernel_launch)
__device__ float g_Q[TOK*NHD];
__device__ float g_K[TOK*NHD];
__device__ float g_V[TOK*NHD];
__device__ float g_X[TOK*NHD];

// ---------------------------------------------------------------------------
// SGEMM: C[M,N] = alpha * (A[M,K] @ B[K,N] + bias[N])   (all row-major fp32)
// 128x128 block tile, BK=16, 256 threads, 8x8 per-thread microtile.
// ---------------------------------------------------------------------------
__global__ __launch_bounds__(256, 2)
void sgemm_bias_kernel(const float* __restrict__ A, const float* __restrict__ Bm,
                       const float* __restrict__ bias, float* __restrict__ C,
                       int M, int N, int K, float alpha)
{
    constexpr int BM = 128, BN = 128, BK = 16;
    __shared__ float As[BK][BM + 4];   // transposed A tile (k-major), padded
    __shared__ float Bs[BK][BN];

    const int tid = threadIdx.x;            // 0..255
    const int bm  = blockIdx.y * BM;
    const int bn  = blockIdx.x * BN;
    const int tx  = tid & 15;
    const int ty  = tid >> 4;

    // global->smem load mapping
    const int arow = tid >> 2;               // 0..63
    const int acol = (tid & 3) * 4;          // 0,4,8,12
    const int brow = tid >> 5;               // 0..7
    const int bcol = (tid & 31) * 4;         // 0..124

    float acc[8][8];
#pragma unroll
    for (int i = 0; i < 8; i++)
#pragma unroll
        for (int j = 0; j < 8; j++) acc[i][j] = 0.f;

    for (int k0 = 0; k0 < K; k0 += BK) {
#pragma unroll
        for (int p = 0; p < 2; p++) {
            float4 a = *reinterpret_cast<const float4*>(
                &A[(long)(bm + arow + p * 64) * K + k0 + acol]);
            As[acol + 0][arow + p * 64] = a.x;
            As[acol + 1][arow + p * 64] = a.y;
            As[acol + 2][arow + p * 64] = a.z;
            As[acol + 3][arow + p * 64] = a.w;
        }
#pragma unroll
        for (int p = 0; p < 2; p++) {
            *reinterpret_cast<float4*>(&Bs[brow + p * 8][bcol]) =
                *reinterpret_cast<const float4*>(
                    &Bm[(long)(k0 + brow + p * 8) * N + bn + bcol]);
        }
        __syncthreads();

#pragma unroll
        for (int kk = 0; kk < BK; kk++) {
            float a[8], b[8];
            *reinterpret_cast<float4*>(&a[0]) =
                *reinterpret_cast<const float4*>(&As[kk][ty * 8]);
            *reinterpret_cast<float4*>(&a[4]) =
                *reinterpret_cast<const float4*>(&As[kk][ty * 8 + 4]);
            *reinterpret_cast<float4*>(&b[0]) =
                *reinterpret_cast<const float4*>(&Bs[kk][tx * 8]);
            *reinterpret_cast<float4*>(&b[4]) =
                *reinterpret_cast<const float4*>(&Bs[kk][tx * 8 + 4]);
#pragma unroll
            for (int i = 0; i < 8; i++)
#pragma unroll
                for (int j = 0; j < 8; j++)
                    acc[i][j] = fmaf(a[i], b[j], acc[i][j]);
        }
        __syncthreads();
    }

#pragma unroll
    for (int i = 0; i < 8; i++) {
        int row = bm + ty * 8 + i;
#pragma unroll
        for (int j = 0; j < 8; j += 4) {
            int col = bn + tx * 8 + j;
            float4 o;
            o.x = alpha * (acc[i][j + 0] + bias[col + 0]);
            o.y = alpha * (acc[i][j + 1] + bias[col + 1]);
            o.z = alpha * (acc[i][j + 2] + bias[col + 2]);
            o.w = alpha * (acc[i][j + 3] + bias[col + 3]);
            *reinterpret_cast<float4*>(&C[(long)row * N + col]) = o;
        }
    }
}

// ---------------------------------------------------------------------------
// Flash attention (fp32): per (b,h), BQ=128 queries per CTA, loop 64-key blocks.
// Q is pre-scaled by 1/sqrt(DH) in the projection. Online softmax.
// Thread layout: 256 thr, tx=tid&15 (4 cols each), ty=tid>>4 (8 rows each).
// ---------------------------------------------------------------------------
__global__ __launch_bounds__(256, 2)
void flash_attn_kernel(const float* __restrict__ Q, const float* __restrict__ K,
                       const float* __restrict__ V, float* __restrict__ X)
{
    extern __shared__ float sm[];
    float* Qs = sm;                  // [64][128]  d-major (transposed)
    float* Ks = Qs + 64 * 128;       // [64][64]   d-major (transposed)
    float* Vs = Ks + 64 * 64;        // [64][64]   kk-major
    float* Ps = Vs + 64 * 64;        // [128][64]  row-major probabilities

    const int tid = threadIdx.x;
    const int tx = tid & 15;
    const int ty = tid >> 4;
    const int bh = blockIdx.y;        // 0..63
    const int b  = bh >> 4;           // / H
    const int h  = bh & 15;           // % H
    const int q0 = blockIdx.x * 128;

    const long base = (long)b * Ss * NHD + (long)h * DHd; // token0 of this head
    const float* Qb = Q + base + (long)q0 * NHD;
    const float* Kb = K + base;
    const float* Vb = V + base;

    // Load Q tile transposed: Qs[d][r]
    for (int idx = tid; idx < 128 * 64 / 4; idx += 256) {
        int r  = idx >> 4;
        int d4 = (idx & 15) * 4;
        float4 v = *reinterpret_cast<const float4*>(&Qb[(long)r * NHD + d4]);
        Qs[(d4 + 0) * 128 + r] = v.x;
        Qs[(d4 + 1) * 128 + r] = v.y;
        Qs[(d4 + 2) * 128 + r] = v.z;
        Qs[(d4 + 3) * 128 + r] = v.w;
    }

    float o[8][4];
    float m[8], l[8];
#pragma unroll
    for (int i = 0; i < 8; i++) {
        m[i] = -1e30f; l[i] = 0.f;
#pragma unroll
        for (int j = 0; j < 4; j++) o[i][j] = 0.f;
    }

    for (int kb = 0; kb < Ss; kb += 64) {
        __syncthreads();   // protect Ks/Vs/Ps reuse (also covers initial Q load)

        // Load K transposed + V direct
        for (int idx = tid; idx < 64 * 64 / 4; idx += 256) {
            int c  = idx >> 4;
            int d4 = (idx & 15) * 4;
            float4 kv = *reinterpret_cast<const float4*>(
                &Kb[(long)(kb + c) * NHD + d4]);
            Ks[(d4 + 0) * 64 + c] = kv.x;
            Ks[(d4 + 1) * 64 + c] = kv.y;
            Ks[(d4 + 2) * 64 + c] = kv.z;
            Ks[(d4 + 3) * 64 + c] = kv.w;
            float4 vv = *reinterpret_cast<const float4*>(
                &Vb[(long)(kb + c) * NHD + d4]);
            *reinterpret_cast<float4*>(&Vs[c * 64 + d4]) = vv;
        }
        __syncthreads();

        // S = Q K^T  (rows ty*8+i, key-cols tx*4+j)
        float s[8][4];
#pragma unroll
        for (int i = 0; i < 8; i++)
#pragma unroll
            for (int j = 0; j < 4; j++) s[i][j] = 0.f;

#pragma unroll 8
        for (int d = 0; d < 64; d++) {
            float a[8], kx[4];
            *reinterpret_cast<float4*>(&a[0]) =
                *reinterpret_cast<const float4*>(&Qs[d * 128 + ty * 8]);
            *reinterpret_cast<float4*>(&a[4]) =
                *reinterpret_cast<const float4*>(&Qs[d * 128 + ty * 8 + 4]);
            *reinterpret_cast<float4*>(&kx[0]) =
                *reinterpret_cast<const float4*>(&Ks[d * 64 + tx * 4]);
#pragma unroll
            for (int i = 0; i < 8; i++)
#pragma unroll
                for (int j = 0; j < 4; j++)
                    s[i][j] = fmaf(a[i], kx[j], s[i][j]);
        }

        // Online softmax (row reductions across the 16 tx lanes)
#pragma unroll
        for (int i = 0; i < 8; i++) {
            float mb = fmaxf(fmaxf(s[i][0], s[i][1]), fmaxf(s[i][2], s[i][3]));
#pragma unroll
            for (int off = 8; off; off >>= 1)
                mb = fmaxf(mb, __shfl_xor_sync(0xffffffffu, mb, off));
            float mn = fmaxf(m[i], mb);
            float al = __expf(m[i] - mn);
            m[i] = mn;
            float p[4];
            float ps = 0.f;
#pragma unroll
            for (int j = 0; j < 4; j++) { p[j] = __expf(s[i][j] - mn); ps += p[j]; }
            *reinterpret_cast<float4*>(&Ps[(ty * 8 + i) * 64 + tx * 4]) =
                *reinterpret_cast<float4*>(p);
#pragma unroll
            for (int off = 8; off; off >>= 1)
                ps += __shfl_xor_sync(0xffffffffu, ps, off);
            l[i] = l[i] * al + ps;
#pragma unroll
            for (int j = 0; j < 4; j++) o[i][j] *= al;
        }
        __syncthreads();

        // O += P @ V  (dh cols tx*4+j)
#pragma unroll 8
        for (int kk = 0; kk < 64; kk++) {
            float vj[4];
            *reinterpret_cast<float4*>(&vj[0]) =
                *reinterpret_cast<const float4*>(&Vs[kk * 64 + tx * 4]);
#pragma unroll
            for (int i = 0; i < 8; i++) {
                float p = Ps[(ty * 8 + i) * 64 + kk];   // broadcast within half-warp
#pragma unroll
                for (int j = 0; j < 4; j++)
                    o[i][j] = fmaf(p, vj[j], o[i][j]);
            }
        }
    }

    // Normalize and write X[b, q, h, :]
    float* Xb = X + base + (long)q0 * NHD;
#pragma unroll
    for (int i = 0; i < 8; i++) {
        float inv = 1.f / l[i];
        float4 w;
        w.x = o[i][0] * inv; w.y = o[i][1] * inv;
        w.z = o[i][2] * inv; w.w = o[i][3] * inv;
        *reinterpret_cast<float4*>(&Xb[(long)(ty * 8 + i) * NHD + tx * 4]) = w;
    }
}

// ---------------------------------------------------------------------------
extern "C" void kernel_launch(void* const* d_in, const int* in_sizes, int n_in,
                              void* d_out, int out_size)
{
    const float* xq = (const float*)d_in[0];
    const float* xkv = (const float*)d_in[1];
    const float* Wq = (const float*)d_in[2];
    const float* bq = (const float*)d_in[3];
    const float* Wk = (const float*)d_in[4];
    const float* bk = (const float*)d_in[5];
    const float* Wv = (const float*)d_in[6];
    const float* bv = (const float*)d_in[7];
    const float* Wo = (const float*)d_in[8];
    const float* bo = (const float*)d_in[9];
    float* out = (float*)d_out;

    float *qp, *kp, *vp, *xp;
    cudaGetSymbolAddress((void**)&qp, g_Q);
    cudaGetSymbolAddress((void**)&kp, g_K);
    cudaGetSymbolAddress((void**)&vp, g_V);
    cudaGetSymbolAddress((void**)&xp, g_X);

    dim3 gg(NHD / 128, TOK / 128);   // (8, 64)

    // QKV projections; fold 1/sqrt(DH) into Q (scale applies after bias in ref)
    sgemm_bias_kernel<<<gg, 256>>>(xq,  Wq, bq, qp, TOK, NHD, Dd, 0.125f);
    sgemm_bias_kernel<<<gg, 256>>>(xkv, Wk, bk, kp, TOK, NHD, Dd, 1.0f);
    sgemm_bias_kernel<<<gg, 256>>>(xkv, Wv, bv, vp, TOK, NHD, Dd, 1.0f);

    // Attention
    cudaFuncSetAttribute(flash_attn_kernel,
                         cudaFuncAttributeMaxDynamicSharedMemorySize, 98304);
    dim3 ga(Ss / 128, Bb * Hh);      // (16, 64)
    flash_attn_kernel<<<ga, 256, 98304>>>(qp, kp, vp, xp);

    // Output projection
    sgemm_bias_kernel<<<gg, 256>>>(xp, Wo, bo, out, TOK, Dd, NHD, 1.0f);
}

// round 8
// speedup vs baseline: 1.0009x; 1.0009x over previous
#include <cuda_runtime.h>

// Problem constants
#define Bb 4
#define Ss 2048
#define Dd 1024
#define Hh 16
#define DHd 64
#define TOK (Bb*Ss)          // 8192
#define NHD (Hh*DHd)         // 1024

// Scratch (device globals — no allocation allowed in kernel_launch)
__device__ float g_Q[TOK*NHD];
__device__ float g_K[TOK*NHD];
__device__ float g_V[TOK*NHD];
__device__ float g_X[TOK*NHD];

// ---------------------------------------------------------------------------
// SGEMM: C[M,N] = alpha * (A[M,K] @ B[K,N] + bias[N])   (all row-major fp32)
// 128x128 block tile, BK=16, 256 threads, 8x8 per-thread microtile.
// ---------------------------------------------------------------------------
__global__ __launch_bounds__(256, 2)
void sgemm_bias_kernel(const float* __restrict__ A, const float* __restrict__ Bm,
                       const float* __restrict__ bias, float* __restrict__ C,
                       int M, int N, int K, float alpha)
{
    constexpr int BM = 128, BN = 128, BK = 16;
    __shared__ float As[BK][BM + 4];   // transposed A tile (k-major), padded
    __shared__ float Bs[BK][BN];

    const int tid = threadIdx.x;            // 0..255
    const int bm  = blockIdx.y * BM;
    const int bn  = blockIdx.x * BN;
    const int tx  = tid & 15;
    const int ty  = tid >> 4;

    // global->smem load mapping
    const int arow = tid >> 2;               // 0..63
    const int acol = (tid & 3) * 4;          // 0,4,8,12
    const int brow = tid >> 5;               // 0..7
    const int bcol = (tid & 31) * 4;         // 0..124

    float acc[8][8];
#pragma unroll
    for (int i = 0; i < 8; i++)
#pragma unroll
        for (int j = 0; j < 8; j++) acc[i][j] = 0.f;

    for (int k0 = 0; k0 < K; k0 += BK) {
#pragma unroll
        for (int p = 0; p < 2; p++) {
            float4 a = *reinterpret_cast<const float4*>(
                &A[(long)(bm + arow + p * 64) * K + k0 + acol]);
            As[acol + 0][arow + p * 64] = a.x;
            As[acol + 1][arow + p * 64] = a.y;
            As[acol + 2][arow + p * 64] = a.z;
            As[acol + 3][arow + p * 64] = a.w;
        }
#pragma unroll
        for (int p = 0; p < 2; p++) {
            *reinterpret_cast<float4*>(&Bs[brow + p * 8][bcol]) =
                *reinterpret_cast<const float4*>(
                    &Bm[(long)(k0 + brow + p * 8) * N + bn + bcol]);
        }
        __syncthreads();

#pragma unroll
        for (int kk = 0; kk < BK; kk++) {
            float a[8], b[8];
            *reinterpret_cast<float4*>(&a[0]) =
                *reinterpret_cast<const float4*>(&As[kk][ty * 8]);
            *reinterpret_cast<float4*>(&a[4]) =
                *reinterpret_cast<const float4*>(&As[kk][ty * 8 + 4]);
            *reinterpret_cast<float4*>(&b[0]) =
                *reinterpret_cast<const float4*>(&Bs[kk][tx * 8]);
            *reinterpret_cast<float4*>(&b[4]) =
                *reinterpret_cast<const float4*>(&Bs[kk][tx * 8 + 4]);
#pragma unroll
            for (int i = 0; i < 8; i++)
#pragma unroll
                for (int j = 0; j < 8; j++)
                    acc[i][j] = fmaf(a[i], b[j], acc[i][j]);
        }
        __syncthreads();
    }

#pragma unroll
    for (int i = 0; i < 8; i++) {
        int row = bm + ty * 8 + i;
#pragma unroll
        for (int j = 0; j < 8; j += 4) {
            int col = bn + tx * 8 + j;
            float4 o;
            o.x = alpha * (acc[i][j + 0] + bias[col + 0]);
            o.y = alpha * (acc[i][j + 1] + bias[col + 1]);
            o.z = alpha * (acc[i][j + 2] + bias[col + 2]);
            o.w = alpha * (acc[i][j + 3] + bias[col + 3]);
            *reinterpret_cast<float4*>(&C[(long)row * N + col]) = o;
        }
    }
}

// ---------------------------------------------------------------------------
// Flash attention (fp32): per (b,h), BQ=128 queries per CTA, loop 64-key blocks.
// Q is pre-scaled by 1/sqrt(DH) in the projection. Online softmax.
// Thread layout: 256 thr, tx=tid&15 (4 cols each), ty=tid>>4 (8 rows each).
// ---------------------------------------------------------------------------
__global__ __launch_bounds__(256, 2)
void flash_attn_kernel(const float* __restrict__ Q, const float* __restrict__ K,
                       const float* __restrict__ V, float* __restrict__ X)
{
    extern __shared__ float sm[];
    float* Qs = sm;                  // [64][128]  d-major (transposed)
    float* Ks = Qs + 64 * 128;       // [64][64]   d-major (transposed)
    float* Vs = Ks + 64 * 64;        // [64][64]   kk-major
    float* Ps = Vs + 64 * 64;        // [128][64]  row-major probabilities

    const int tid = threadIdx.x;
    const int tx = tid & 15;
    const int ty = tid >> 4;
    const int bh = blockIdx.y;        // 0..63
    const int b  = bh >> 4;           // / H
    const int h  = bh & 15;           // % H
    const int q0 = blockIdx.x * 128;

    const long base = (long)b * Ss * NHD + (long)h * DHd; // token0 of this head
    const float* Qb = Q + base + (long)q0 * NHD;
    const float* Kb = K + base;
    const float* Vb = V + base;

    // Load Q tile transposed: Qs[d][r]
    for (int idx = tid; idx < 128 * 64 / 4; idx += 256) {
        int r  = idx >> 4;
        int d4 = (idx & 15) * 4;
        float4 v = *reinterpret_cast<const float4*>(&Qb[(long)r * NHD + d4]);
        Qs[(d4 + 0) * 128 + r] = v.x;
        Qs[(d4 + 1) * 128 + r] = v.y;
        Qs[(d4 + 2) * 128 + r] = v.z;
        Qs[(d4 + 3) * 128 + r] = v.w;
    }

    float o[8][4];
    float m[8], l[8];
#pragma unroll
    for (int i = 0; i < 8; i++) {
        m[i] = -1e30f; l[i] = 0.f;
#pragma unroll
        for (int j = 0; j < 4; j++) o[i][j] = 0.f;
    }

    for (int kb = 0; kb < Ss; kb += 64) {
        __syncthreads();   // protect Ks/Vs/Ps reuse (also covers initial Q load)

        // Load K transposed + V direct
        for (int idx = tid; idx < 64 * 64 / 4; idx += 256) {
            int c  = idx >> 4;
            int d4 = (idx & 15) * 4;
            float4 kv = *reinterpret_cast<const float4*>(
                &Kb[(long)(kb + c) * NHD + d4]);
            Ks[(d4 + 0) * 64 + c] = kv.x;
            Ks[(d4 + 1) * 64 + c] = kv.y;
            Ks[(d4 + 2) * 64 + c] = kv.z;
            Ks[(d4 + 3) * 64 + c] = kv.w;
            float4 vv = *reinterpret_cast<const float4*>(
                &Vb[(long)(kb + c) * NHD + d4]);
            *reinterpret_cast<float4*>(&Vs[c * 64 + d4]) = vv;
        }
        __syncthreads();

        // S = Q K^T  (rows ty*8+i, key-cols tx*4+j)
        float s[8][4];
#pragma unroll
        for (int i = 0; i < 8; i++)
#pragma unroll
            for (int j = 0; j < 4; j++) s[i][j] = 0.f;

#pragma unroll 8
        for (int d = 0; d < 64; d++) {
            float a[8], kx[4];
            *reinterpret_cast<float4*>(&a[0]) =
                *reinterpret_cast<const float4*>(&Qs[d * 128 + ty * 8]);
            *reinterpret_cast<float4*>(&a[4]) =
                *reinterpret_cast<const float4*>(&Qs[d * 128 + ty * 8 + 4]);
            *reinterpret_cast<float4*>(&kx[0]) =
                *reinterpret_cast<const float4*>(&Ks[d * 64 + tx * 4]);
#pragma unroll
            for (int i = 0; i < 8; i++)
#pragma unroll
                for (int j = 0; j < 4; j++)
                    s[i][j] = fmaf(a[i], kx[j], s[i][j]);
        }

        // Online softmax (row reductions across the 16 tx lanes)
#pragma unroll
        for (int i = 0; i < 8; i++) {
            float mb = fmaxf(fmaxf(s[i][0], s[i][1]), fmaxf(s[i][2], s[i][3]));
#pragma unroll
            for (int off = 8; off; off >>= 1)
                mb = fmaxf(mb, __shfl_xor_sync(0xffffffffu, mb, off));
            float mn = fmaxf(m[i], mb);
            float al = __expf(m[i] - mn);
            m[i] = mn;
            float p[4];
            float ps = 0.f;
#pragma unroll
            for (int j = 0; j < 4; j++) { p[j] = __expf(s[i][j] - mn); ps += p[j]; }
            *reinterpret_cast<float4*>(&Ps[(ty * 8 + i) * 64 + tx * 4]) =
                *reinterpret_cast<float4*>(p);
#pragma unroll
            for (int off = 8; off; off >>= 1)
                ps += __shfl_xor_sync(0xffffffffu, ps, off);
            l[i] = l[i] * al + ps;
#pragma unroll
            for (int j = 0; j < 4; j++) o[i][j] *= al;
        }
        __syncthreads();

        // O += P @ V  (dh cols tx*4+j)
#pragma unroll 8
        for (int kk = 0; kk < 64; kk++) {
            float vj[4];
            *reinterpret_cast<float4*>(&vj[0]) =
                *reinterpret_cast<const float4*>(&Vs[kk * 64 + tx * 4]);
#pragma unroll
            for (int i = 0; i < 8; i++) {
                float p = Ps[(ty * 8 + i) * 64 + kk];   // broadcast within half-warp
#pragma unroll
                for (int j = 0; j < 4; j++)
                    o[i][j] = fmaf(p, vj[j], o[i][j]);
            }
        }
    }

    // Normalize and write X[b, q, h, :]
    float* Xb = X + base + (long)q0 * NHD;
#pragma unroll
    for (int i = 0; i < 8; i++) {
        float inv = 1.f / l[i];
        float4 w;
        w.x = o[i][0] * inv; w.y = o[i][1] * inv;
        w.z = o[i][2] * inv; w.w = o[i][3] * inv;
        *reinterpret_cast<float4*>(&Xb[(long)(ty * 8 + i) * NHD + tx * 4]) = w;
    }
}

// ---------------------------------------------------------------------------
extern "C" void kernel_launch(void* const* d_in, const int* in_sizes, int n_in,
                              void* d_out, int out_size)
{
    const float* xq = (const float*)d_in[0];
    const float* xkv = (const float*)d_in[1];
    const float* Wq = (const float*)d_in[2];
    const float* bq = (const float*)d_in[3];
    const float* Wk = (const float*)d_in[4];
    const float* bk = (const float*)d_in[5];
    const float* Wv = (const float*)d_in[6];
    const float* bv = (const float*)d_in[7];
    const float* Wo = (const float*)d_in[8];
    const float* bo = (const float*)d_in[9];
    float* out = (float*)d_out;

    float *qp, *kp, *vp, *xp;
    cudaGetSymbolAddress((void**)&qp, g_Q);
    cudaGetSymbolAddress((void**)&kp, g_K);
    cudaGetSymbolAddress((void**)&vp, g_V);
    cudaGetSymbolAddress((void**)&xp, g_X);

    dim3 gg(NHD / 128, TOK / 128);   // (8, 64)

    // QKV projections; fold 1/sqrt(DH) into Q (scale applies after bias in ref)
    sgemm_bias_kernel<<<gg, 256>>>(xq,  Wq, bq, qp, TOK, NHD, Dd, 0.125f);
    sgemm_bias_kernel<<<gg, 256>>>(xkv, Wk, bk, kp, TOK, NHD, Dd, 1.0f);
    sgemm_bias_kernel<<<gg, 256>>>(xkv, Wv, bv, vp, TOK, NHD, Dd, 1.0f);

    // Attention
    cudaFuncSetAttribute(flash_attn_kernel,
                         cudaFuncAttributeMaxDynamicSharedMemorySize, 98304);
    dim3 ga(Ss / 128, Bb * Hh);      // (16, 64)
    flash_attn_kernel<<<ga, 256, 98304>>>(qp, kp, vp, xp);

    // Output projection
    sgemm_bias_kernel<<<gg, 256>>>(xp, Wo, bo, out, TOK, Dd, NHD, 1.0f);
}